// round 6
// baseline (speedup 1.0000x reference)
#include <cuda_runtime.h>
#include <cuda_fp16.h>
#include <cstdint>

// ---------------- problem constants ----------------
#define IN_F   4096
#define OUT_F  16384
#define NTOK   64
#define RANK   64

#define BLOCK_M 128          // out-features per CTA
#define KBLK    32           // K elems per pipeline stage
#define STAGES  4
#define NCHUNK_MAIN (IN_F / KBLK)             // 128
#define NCHUNK_TOT  (NCHUNK_MAIN + RANK/KBLK) // 130

// ---------------- SMEM layout ----------------
#define P32        36                          // fp32 row pitch (floats)
#define W32_STAGE_F (BLOCK_M * P32)            // 4608 floats
#define W32_STAGE_B (W32_STAGE_F * 4)          // 18432 B
#define OFF_W32    0
#define PH         40                          // fp16 row pitch (halfs)
#define WH_BYTES   (BLOCK_M * PH * 2)          // 10240 B
#define OFF_WH     (STAGES * W32_STAGE_B)      // 73728 (x2 buffers)
#define OFF_XH     (OFF_WH + 2 * WH_BYTES)     // 94208
#define XH_STAGE_B (NTOK * PH * 2)             // 5120 B
#define SMEM_BYTES (OFF_XH + STAGES * XH_STAGE_B)  // 114688

// device scratch
__device__ __align__(256) __half g_xh[NTOK * IN_F];   // x in fp16
__device__ __align__(256) __half g_t2h[NTOK * RANK];  // 2*(x@A^T) in fp16

// ---------------- PTX helpers ----------------
__device__ __forceinline__ uint32_t smem_u32(const void* p) {
    uint32_t a;
    asm("{ .reg .u64 t; cvta.to.shared.u64 t, %1; cvt.u32.u64 %0, t; }" : "=r"(a) : "l"(p));
    return a;
}
__device__ __forceinline__ void cp16(uint32_t dst, const void* src) {
    asm volatile("cp.async.cg.shared.global [%0], [%1], 16;" :: "r"(dst), "l"(src));
}
#define CP_COMMIT() asm volatile("cp.async.commit_group;" ::: "memory")
#define CP_WAIT1()  asm volatile("cp.async.wait_group 1;" ::: "memory")

__device__ __forceinline__ void ldsm4(uint32_t* r, uint32_t addr) {
    asm volatile("ldmatrix.sync.aligned.m8n8.x4.shared.b16 {%0,%1,%2,%3}, [%4];"
                 : "=r"(r[0]), "=r"(r[1]), "=r"(r[2]), "=r"(r[3]) : "r"(addr));
}
__device__ __forceinline__ void mma_f16(float* d, const uint32_t* a,
                                        uint32_t b0, uint32_t b1) {
    asm volatile(
        "mma.sync.aligned.m16n8k16.row.col.f32.f16.f16.f32 "
        "{%0,%1,%2,%3}, {%4,%5,%6,%7}, {%8,%9}, {%0,%1,%2,%3};"
        : "+f"(d[0]), "+f"(d[1]), "+f"(d[2]), "+f"(d[3])
        : "r"(a[0]), "r"(a[1]), "r"(a[2]), "r"(a[3]), "r"(b0), "r"(b1));
}
__device__ __forceinline__ uint32_t h2u(__half2 h) {
    return *reinterpret_cast<uint32_t*>(&h);
}

// ---------------- prep 1: x -> fp16 ----------------
__global__ void __launch_bounds__(256) x2h_kernel(const float4* __restrict__ x4,
                                                  uint2* __restrict__ xh2) {
    int i = blockIdx.x * 256 + threadIdx.x;
    float4 v = x4[i];
    uint2 o;
    o.x = h2u(__floats2half2_rn(v.x, v.y));
    o.y = h2u(__floats2half2_rn(v.z, v.w));
    xh2[i] = o;
}

// ---------------- prep 2: t2h = fp16( 2 * (x @ A^T) ) ----------------
__global__ void __launch_bounds__(256) lora_t_kernel(const float* __restrict__ x,
                                                     const float* __restrict__ A,
                                                     __half* __restrict__ t2) {
    __shared__ float red[256];
    int tid  = threadIdx.x;
    int pair = tid & 63;
    int i  = pair >> 3;
    int j  = pair & 7;
    int kg = tid >> 6;
    int gi = (blockIdx.x >> 3) * 8 + i;
    int gj = (blockIdx.x & 7) * 8 + j;

    const float4* xr = (const float4*)(x + (size_t)gi * IN_F);
    const float4* ar = (const float4*)(A + (size_t)gj * IN_F);
    float acc = 0.f;
    int k0 = kg * 256;
#pragma unroll 4
    for (int k = k0; k < k0 + 256; ++k) {
        float4 a = xr[k];
        float4 b = ar[k];
        acc += a.x * b.x + a.y * b.y + a.z * b.z + a.w * b.w;
    }
    red[tid] = acc;
    __syncthreads();
    if (kg == 0) {
        float s = red[pair] + red[pair + 64] + red[pair + 128] + red[pair + 192];
        t2[gi * RANK + gj] = __float2half_rn(2.0f * s);
    }
}

// ---------------- main fused GEMM ----------------
// 128 CTAs, 256 threads (8 warps: 4 along M x 2 along N).
// Single barrier/iter. Every smem consume sits behind a barrier that followed a
// cp.async wait covering that stage (cross-thread visibility — the R5 race fix).
__global__ void __launch_bounds__(256, 1) lora_main_kernel(
    const __half* __restrict__ xh,     // [64,4096] fp16
    const float*  __restrict__ w,      // [16384,4096] fp32
    const float*  __restrict__ lB,     // [16384,64] fp32
    const __half* __restrict__ t2h,    // [64,64] fp16 (incl. 2x scale)
    float* __restrict__ out)           // [64,16384]
{
    extern __shared__ __align__(16) char smem_c[];
    float* smem_f = (float*)smem_c;
    const uint32_t sb = smem_u32(smem_c);
    const int tid  = threadIdx.x;
    const int wid  = tid >> 5;
    const int lane = tid & 31;
    const int g = lane >> 2;
    const int t = lane & 3;
    const int wm = (wid & 3) * 32;    // warp M offset
    const int wn = (wid >> 2) * 32;   // warp N offset (tokens)
    const int m_base = blockIdx.x * BLOCK_M;

    // ---- per-lane ldmatrix offsets ----
    const int a_row  = (lane & 7) + ((lane >> 3) & 1) * 8;
    const uint32_t a_byte = ((lane >> 4) & 1) * 16;
    const uint32_t a_rel0 = (uint32_t)(wm + a_row) * (PH * 2) + a_byte;
    const uint32_t a_rel1 = a_rel0 + 16 * (PH * 2);
    const int b_row  = (lane & 7) + ((lane >> 4) & 1) * 8;
    const uint32_t b_byte = ((lane >> 3) & 1) * 16;
    const uint32_t b_rel0 = (uint32_t)(wn + b_row) * (PH * 2) + b_byte;
    const uint32_t b_rel1 = b_rel0 + 16 * (PH * 2);

    // ---- stage loader ----
    auto load_stage = [&](int chunk, int stage) {
        const float* a_base; int a_stride;
        const __half* b_base; int b_stride;
        int k0;
        if (chunk < NCHUNK_MAIN) {
            a_base = w + (size_t)m_base * IN_F;  a_stride = IN_F;
            b_base = xh;                         b_stride = IN_F;
            k0 = chunk * KBLK;
        } else {
            a_base = lB + (size_t)m_base * RANK; a_stride = RANK;
            b_base = t2h;                        b_stride = RANK;
            k0 = (chunk - NCHUNK_MAIN) * KBLK;
        }
        uint32_t s_w = sb + OFF_W32 + (uint32_t)stage * W32_STAGE_B;
#pragma unroll
        for (int i = 0; i < 4; ++i) {
            int idx = tid + i * 256;
            int row = idx >> 3, c = idx & 7;
            cp16(s_w + (uint32_t)(row * P32 + c * 4) * 4,
                 a_base + (size_t)row * a_stride + k0 + c * 4);
        }
        uint32_t s_x = sb + OFF_XH + (uint32_t)stage * XH_STAGE_B;
        {
            int row = tid >> 2, seg = tid & 3;
            cp16(s_x + (uint32_t)(row * PH + seg * 8) * 2,
                 b_base + (size_t)row * b_stride + k0 + seg * 8);
        }
    };

    const int cvt_row = tid >> 1;
    const int cvt_c   = tid & 1;
    auto convert = [&](int slot, int buf) {
        const float* srcp = smem_f + slot * W32_STAGE_F + cvt_row * P32 + cvt_c * 16;
        float4 v0 = ((const float4*)srcp)[0];
        float4 v1 = ((const float4*)srcp)[1];
        float4 v2 = ((const float4*)srcp)[2];
        float4 v3 = ((const float4*)srcp)[3];
        uint4 p0, p1;
        p0.x = h2u(__floats2half2_rn(v0.x, v0.y));
        p0.y = h2u(__floats2half2_rn(v0.z, v0.w));
        p0.z = h2u(__floats2half2_rn(v1.x, v1.y));
        p0.w = h2u(__floats2half2_rn(v1.z, v1.w));
        p1.x = h2u(__floats2half2_rn(v2.x, v2.y));
        p1.y = h2u(__floats2half2_rn(v2.z, v2.w));
        p1.z = h2u(__floats2half2_rn(v3.x, v3.y));
        p1.w = h2u(__floats2half2_rn(v3.z, v3.w));
        __half* whp = (__half*)(smem_c + OFF_WH + buf * WH_BYTES) + cvt_row * PH + cvt_c * 16;
        ((uint4*)whp)[0] = p0;
        ((uint4*)(whp + 8))[0] = p1;
    };

    // ---- prologue: stages 0,1,2 in flight; stages 0,1 landed+published; Wh0 ready ----
#pragma unroll
    for (int s = 0; s < STAGES - 1; ++s) {
        load_stage(s, s);
        CP_COMMIT();
    }
    CP_WAIT1();            // own groups for stages 0,1 complete
    __syncthreads();       // ALL threads' stages 0,1 visible
    convert(0, 0);
    __syncthreads();       // Wh0 published

    float d[2][4][4];
#pragma unroll
    for (int mi = 0; mi < 2; ++mi)
#pragma unroll
        for (int ni = 0; ni < 4; ++ni)
#pragma unroll
            for (int r = 0; r < 4; ++r) d[mi][ni][r] = 0.f;

    // ---- mainloop ----
    for (int it = 0; it < NCHUNK_TOT; ++it) {
        // convert stage it+1 (visible: waited + barrier'd last iteration / prologue)
        if (it + 1 < NCHUNK_TOT) convert((it + 1) & (STAGES - 1), (it + 1) & 1);

        // MMA on stage it (Wh[it&1] published by barrier at end of prev iter)
        const uint32_t wh_b = sb + OFF_WH + (uint32_t)(it & 1) * WH_BYTES;
        const uint32_t xb   = sb + OFF_XH + (uint32_t)(it & (STAGES - 1)) * XH_STAGE_B;
#pragma unroll
        for (int kk = 0; kk < 2; ++kk) {
            const uint32_t k2 = kk * 32;   // 16 halfs = 32B
            uint32_t a0[4], a1[4], bq0[4], bq1[4];
            ldsm4(a0,  wh_b + a_rel0 + k2);
            ldsm4(a1,  wh_b + a_rel1 + k2);
            ldsm4(bq0, xb + b_rel0 + k2);
            ldsm4(bq1, xb + b_rel1 + k2);
            mma_f16(d[0][0], a0, bq0[0], bq0[1]);
            mma_f16(d[0][1], a0, bq0[2], bq0[3]);
            mma_f16(d[0][2], a0, bq1[0], bq1[1]);
            mma_f16(d[0][3], a0, bq1[2], bq1[3]);
            mma_f16(d[1][0], a1, bq0[0], bq0[1]);
            mma_f16(d[1][1], a1, bq0[2], bq0[3]);
            mma_f16(d[1][2], a1, bq1[0], bq1[1]);
            mma_f16(d[1][3], a1, bq1[2], bq1[3]);
        }

        // refill stage it+3 into slot (it+3)&3 (last read ≥1 barrier ago)
        {
            int nc = it + STAGES - 1;
            if (nc < NCHUNK_TOT) load_stage(nc, nc & (STAGES - 1));
            CP_COMMIT();
        }
        CP_WAIT1();        // own group for stage it+2 complete
        __syncthreads();   // publish: everyone's stage it+2 data + Wh[(it+1)&1]
    }

    // ---- epilogue: D[m][n] -> out[n][m] ----
#pragma unroll
    for (int mi = 0; mi < 2; ++mi) {
#pragma unroll
        for (int ni = 0; ni < 4; ++ni) {
            int m = m_base + wm + mi * 16 + g;
            int n = wn + ni * 8 + 2 * t;
            out[(size_t)n * OUT_F + m]           = d[mi][ni][0];
            out[(size_t)(n + 1) * OUT_F + m]     = d[mi][ni][1];
            out[(size_t)n * OUT_F + m + 8]       = d[mi][ni][2];
            out[(size_t)(n + 1) * OUT_F + m + 8] = d[mi][ni][3];
        }
    }
}

// ---------------- host launch ----------------
extern "C" void kernel_launch(void* const* d_in, const int* in_sizes, int n_in,
                              void* d_out, int out_size) {
    const float* x  = (const float*)d_in[0];   // [64, 4096]
    const float* w  = (const float*)d_in[1];   // [16384, 4096]
    const float* lA = (const float*)d_in[2];   // [64, 4096]
    const float* lB = (const float*)d_in[3];   // [16384, 64]
    float* out = (float*)d_out;                // [64, 16384]

    void* xh_ptr = nullptr;
    void* t2_ptr = nullptr;
    cudaGetSymbolAddress(&xh_ptr, g_xh);
    cudaGetSymbolAddress(&t2_ptr, g_t2h);

    x2h_kernel<<<(NTOK * IN_F / 4) / 256, 256>>>((const float4*)x, (uint2*)xh_ptr);
    lora_t_kernel<<<64, 256>>>(x, lA, (__half*)t2_ptr);

    static int smem_set = 0;
    if (!smem_set) {
        cudaFuncSetAttribute(lora_main_kernel,
                             cudaFuncAttributeMaxDynamicSharedMemorySize, SMEM_BYTES);
        smem_set = 1;
    }
    lora_main_kernel<<<OUT_F / BLOCK_M, 256, SMEM_BYTES>>>(
        (const __half*)xh_ptr, w, lB, (const __half*)t2_ptr, out);
}